// round 3
// baseline (speedup 1.0000x reference)
#include <cuda_runtime.h>
#include <math.h>

#define T_STEPS 4096
#define HID 2048
#define INP 1024
#define NCTA 148
#define NTHR 256
#define MAXROWS 26

// ---------------- scratch (device globals; no allocation) ----------------
__device__ float g_xproj[(size_t)T_STEPS * HID];   // 32 MB
__device__ unsigned int g_flag[NCTA];

// CTAs per module, proportional to duty cycle (module m active every 2^m steps)
__constant__ int c_mod_start[9] = {0, 44, 74, 94, 108, 118, 128, 138, 148};

// ---------------- kernel R: reset flags ----------------
__global__ void reset_flags() {
    if (threadIdx.x < NCTA) g_flag[threadIdx.x] = 0u;
}

// ---------------- kernel A: Xproj = x @ W_ih^T + b_ih + b_hh ----------------
#define BM 128
#define BN 64
#define BK 16

__global__ void __launch_bounds__(256) gemm_xproj(
    const float* __restrict__ x,      // [T, INP]
    const float* __restrict__ Wih,    // [HID, INP]
    const float* __restrict__ b1,     // [HID]
    const float* __restrict__ b2)     // [HID]
{
    __shared__ float As[BK][BM];
    __shared__ float Bs[BK][BN];
    const int tb = blockIdx.y * BM;
    const int rb = blockIdx.x * BN;
    const int tid = threadIdx.x;
    const int tx = tid & 15;     // n group (x16)
    const int ty = tid >> 4;     // m group (x16)

    float acc[8][4];
#pragma unroll
    for (int i = 0; i < 8; ++i)
#pragma unroll
        for (int j = 0; j < 4; ++j) acc[i][j] = 0.f;

    for (int k0 = 0; k0 < INP; k0 += BK) {
        // load A tile (128x16) transposed into As[k][m]
#pragma unroll
        for (int l = 0; l < 2; ++l) {
            int idx = tid + l * 256;          // 0..511 float4s
            int row = idx >> 2;
            int kc  = (idx & 3) << 2;
            float4 v = *(const float4*)&x[(size_t)(tb + row) * INP + k0 + kc];
            As[kc + 0][row] = v.x; As[kc + 1][row] = v.y;
            As[kc + 2][row] = v.z; As[kc + 3][row] = v.w;
        }
        // load B tile (64x16) transposed into Bs[k][n]
        {
            int row = tid >> 2;
            int kc  = (tid & 3) << 2;
            float4 v = *(const float4*)&Wih[(size_t)(rb + row) * INP + k0 + kc];
            Bs[kc + 0][row] = v.x; Bs[kc + 1][row] = v.y;
            Bs[kc + 2][row] = v.z; Bs[kc + 3][row] = v.w;
        }
        __syncthreads();
#pragma unroll
        for (int kk = 0; kk < BK; ++kk) {
            float a[8], b[4];
#pragma unroll
            for (int i = 0; i < 8; ++i) a[i] = As[kk][ty + 16 * i];
#pragma unroll
            for (int j = 0; j < 4; ++j) b[j] = Bs[kk][tx + 16 * j];
#pragma unroll
            for (int i = 0; i < 8; ++i)
#pragma unroll
                for (int j = 0; j < 4; ++j) acc[i][j] += a[i] * b[j];
        }
        __syncthreads();
    }
#pragma unroll
    for (int i = 0; i < 8; ++i) {
        int t = tb + ty + 16 * i;
#pragma unroll
        for (int j = 0; j < 4; ++j) {
            int r = rb + tx + 16 * j;
            g_xproj[(size_t)t * HID + r] = acc[i][j] + b1[r] + b2[r];
        }
    }
}

// ---------------- kernel B: persistent clockwork recurrence ----------------
__global__ void __launch_bounds__(NTHR, 1) cwrnn_recur(
    const float* __restrict__ Whh,    // [HID, HID]
    float* __restrict__ out)          // [T, HID]
{
    extern __shared__ float sm[];
    float* Wsm  = sm;                          // nr * HID (<= 26*2048)
    float* hsm  = sm + MAXROWS * HID;          // HID
    float* hloc = hsm + HID;                   // 32 pad
    float* xv   = hloc + 32;                   // 32 pad

    const int tid = threadIdx.x;
    const int c = blockIdx.x;

    int m = 0;
#pragma unroll
    for (int j = 1; j < 8; ++j)
        if (c >= c_mod_start[j]) m = j;
    const int N  = c_mod_start[m + 1] - c_mod_start[m];
    const int i  = c - c_mod_start[m];
    const int r0 = m * 256 + (256 * i) / N;
    const int r1 = m * 256 + (256 * (i + 1)) / N;
    const int nr = r1 - r0;
    const unsigned pmask = (1u << m) - 1u;

    // stage this CTA's W_hh rows into SMEM (once)
    {
        const float4* src = (const float4*)(Whh + (size_t)r0 * HID);
        float4* dst = (float4*)Wsm;
        for (int idx = tid; idx < nr * (HID / 4); idx += NTHR) dst[idx] = src[idx];
    }
    if (tid < nr) hloc[tid] = 0.f;
    __syncthreads();

    const int lane = tid & 31, wid = tid >> 5;
    unsigned myflag = 0;   // cached g_flag[tid] (tid < NCTA)

    for (int s = 1; s <= T_STEPS; ++s) {
        float* orow = out + (size_t)(s - 1) * HID;
        if ((s & pmask) == 0u) {
            // prefetch xproj for this step BEFORE the dependency wait
            float xr = 0.f;
            if (tid < nr) xr = g_xproj[(size_t)(s - 1) * HID + r0 + tid];

            if (s > 1) {
                const unsigned target = (unsigned)(s - 1);
                if (tid < NCTA) {
                    while (myflag < target) {
                        unsigned v;
                        asm volatile("ld.acquire.gpu.b32 %0, [%1];"
                                     : "=r"(v) : "l"(g_flag + tid) : "memory");
                        myflag = v;
                    }
                }
                __syncthreads();
                // load h_prev = out[s-2]
                const float4* hp = (const float4*)(out + (size_t)(s - 2) * HID);
                ((float4*)hsm)[tid]       = hp[tid];
                ((float4*)hsm)[tid + 256] = hp[tid + 256];
            } else {
                float4 z = make_float4(0.f, 0.f, 0.f, 0.f);
                ((float4*)hsm)[tid]       = z;
                ((float4*)hsm)[tid + 256] = z;
            }
            if (tid < nr) xv[tid] = xr;
            __syncthreads();

            // matvec: one warp per row, W from SMEM
            for (int r = wid; r < nr; r += 8) {
                const float4* wr = (const float4*)(Wsm + (size_t)r * HID);
                const float4* hv = (const float4*)hsm;
                float a0 = 0.f, a1 = 0.f, a2 = 0.f, a3 = 0.f;
#pragma unroll
                for (int it = 0; it < 16; ++it) {
                    float4 w4 = wr[lane + 32 * it];
                    float4 h4 = hv[lane + 32 * it];
                    a0 += w4.x * h4.x; a1 += w4.y * h4.y;
                    a2 += w4.z * h4.z; a3 += w4.w * h4.w;
                }
                float acc = (a0 + a1) + (a2 + a3);
                acc += __shfl_xor_sync(0xffffffffu, acc, 16);
                acc += __shfl_xor_sync(0xffffffffu, acc, 8);
                acc += __shfl_xor_sync(0xffffffffu, acc, 4);
                acc += __shfl_xor_sync(0xffffffffu, acc, 2);
                acc += __shfl_xor_sync(0xffffffffu, acc, 1);
                if (lane == 0) hloc[r] = tanhf(acc + xv[r]);
            }
            __syncthreads();
        }
        // publish chunk for this step (inactive CTAs just carry state forward)
        if (tid < nr) orow[r0 + tid] = hloc[tid];
        __syncthreads();
        if (tid == 0) {
            asm volatile("st.release.gpu.b32 [%0], %1;"
                         :: "l"(g_flag + c), "r"((unsigned)s) : "memory");
        }
    }
}

// ---------------- launch ----------------
extern "C" void kernel_launch(void* const* d_in, const int* in_sizes, int n_in,
                              void* d_out, int out_size) {
    const float* x    = (const float*)d_in[0];
    const float* Wih  = (const float*)d_in[1];
    const float* Whh  = (const float*)d_in[2];
    const float* b_ih = (const float*)d_in[3];
    const float* b_hh = (const float*)d_in[4];
    float* out = (float*)d_out;

    static bool attr_set = false;
    const int smem_bytes = (MAXROWS * HID + HID + 64) * (int)sizeof(float); // 221440
    if (!attr_set) {
        cudaFuncSetAttribute(cwrnn_recur,
                             cudaFuncAttributeMaxDynamicSharedMemorySize, smem_bytes);
        attr_set = true;
    }

    reset_flags<<<1, 256>>>();
    gemm_xproj<<<dim3(HID / BN, T_STEPS / BM), 256>>>(x, Wih, b_ih, b_hh);
    cwrnn_recur<<<NCTA, NTHR, smem_bytes>>>(Whh, out);
}

// round 4
// speedup vs baseline: 1.8190x; 1.8190x over previous
#include <cuda_runtime.h>
#include <math.h>

#define T_STEPS 4096
#define HID 2048
#define INP 1024
#define NCTA 148
#define NTHR 256
#define MAXROWS 26
#define RCAP 16

// ---------------- scratch (device globals; no allocation) ----------------
__device__ float g_xproj[(size_t)T_STEPS * HID];   // 32 MB
__device__ unsigned int g_cnt[8];                  // per-module monotonic counters

// CTAs per module (duty-cycle weighted; modules 0-2 take the register-W path)
__constant__ int c_start[9] = {0, 48, 76, 92, 106, 118, 128, 138, 148};
__constant__ int c_n[8]     = {48, 28, 16, 14, 12, 10, 10, 10};

__global__ void reset_cnt() {
    if (threadIdx.x < 8) g_cnt[threadIdx.x] = 0u;
}

__device__ __forceinline__ unsigned ld_acq(const unsigned* p) {
    unsigned v;
    asm volatile("ld.acquire.gpu.b32 %0, [%1];" : "=r"(v) : "l"(p) : "memory");
    return v;
}
__device__ __forceinline__ void red_rel_add(unsigned* p, unsigned v) {
    asm volatile("red.release.gpu.global.add.u32 [%0], %1;" :: "l"(p), "r"(v) : "memory");
}

// ---------------- kernel A: Xproj = x @ W_ih^T + b_ih + b_hh ----------------
#define BM 128
#define BN 64
#define BK 16

__global__ void __launch_bounds__(256) gemm_xproj(
    const float* __restrict__ x,      // [T, INP]
    const float* __restrict__ Wih,    // [HID, INP]
    const float* __restrict__ b1,     // [HID]
    const float* __restrict__ b2)     // [HID]
{
    __shared__ float As[BK][BM];
    __shared__ float Bs[BK][BN];
    const int tb = blockIdx.y * BM;
    const int rb = blockIdx.x * BN;
    const int tid = threadIdx.x;
    const int tx = tid & 15;
    const int ty = tid >> 4;

    float acc[8][4];
#pragma unroll
    for (int i = 0; i < 8; ++i)
#pragma unroll
        for (int j = 0; j < 4; ++j) acc[i][j] = 0.f;

    for (int k0 = 0; k0 < INP; k0 += BK) {
#pragma unroll
        for (int l = 0; l < 2; ++l) {
            int idx = tid + l * 256;
            int row = idx >> 2;
            int kc  = (idx & 3) << 2;
            float4 v = *(const float4*)&x[(size_t)(tb + row) * INP + k0 + kc];
            As[kc + 0][row] = v.x; As[kc + 1][row] = v.y;
            As[kc + 2][row] = v.z; As[kc + 3][row] = v.w;
        }
        {
            int row = tid >> 2;
            int kc  = (tid & 3) << 2;
            float4 v = *(const float4*)&Wih[(size_t)(rb + row) * INP + k0 + kc];
            Bs[kc + 0][row] = v.x; Bs[kc + 1][row] = v.y;
            Bs[kc + 2][row] = v.z; Bs[kc + 3][row] = v.w;
        }
        __syncthreads();
#pragma unroll
        for (int kk = 0; kk < BK; ++kk) {
            float a[8], b[4];
#pragma unroll
            for (int i = 0; i < 8; ++i) a[i] = As[kk][ty + 16 * i];
#pragma unroll
            for (int j = 0; j < 4; ++j) b[j] = Bs[kk][tx + 16 * j];
#pragma unroll
            for (int i = 0; i < 8; ++i)
#pragma unroll
                for (int j = 0; j < 4; ++j) acc[i][j] += a[i] * b[j];
        }
        __syncthreads();
    }
#pragma unroll
    for (int i = 0; i < 8; ++i) {
        int t = tb + ty + 16 * i;
#pragma unroll
        for (int j = 0; j < 4; ++j) {
            int r = rb + tx + 16 * j;
            g_xproj[(size_t)t * HID + r] = acc[i][j] + b1[r] + b2[r];
        }
    }
}

// ---------------- kernel B: persistent clockwork recurrence ----------------
__global__ void __launch_bounds__(NTHR, 1) cwrnn_recur(
    const float* __restrict__ Whh,    // [HID, HID]
    float* __restrict__ out)          // [T, HID]
{
    extern __shared__ float sm[];
    float* Wsm  = sm;                          // MAXROWS * HID  (smem-W path)
    float* hsm  = sm + MAXROWS * HID;          // HID            (smem-W path)
    float* xv   = hsm + HID;                   // 32
    float* hloc = xv + 32;                     // 32
    float* redp = hloc + 32;                   // RCAP*8 = 128

    const int tid = threadIdx.x;
    const int c = blockIdx.x;
    const int lane = tid & 31, wid = tid >> 5;

    int m = 0;
#pragma unroll
    for (int j = 1; j < 8; ++j)
        if (c >= c_start[j]) m = j;
    const int N  = c_n[m];
    const int i  = c - c_start[m];
    const int r0 = m * 256 + (256 * i) / N;
    const int r1 = m * 256 + (256 * (i + 1)) / N;
    const int nr = r1 - r0;
    const unsigned pmask = (1u << m) - 1u;
    const bool regpath = (nr <= RCAP);

    // W storage: registers (nr <= RCAP) or SMEM
    float4 Wa[RCAP], Wb[RCAP];
    if (regpath) {
#pragma unroll
        for (int r = 0; r < RCAP; ++r)
            if (r < nr) {
                const float4* src = (const float4*)(Whh + (size_t)(r0 + r) * HID + 8 * tid);
                Wa[r] = src[0];
                Wb[r] = src[1];
            }
    } else {
        const float4* src = (const float4*)(Whh + (size_t)r0 * HID);
        float4* dst = (float4*)Wsm;
        for (int idx = tid; idx < nr * (HID / 4); idx += NTHR) dst[idx] = src[idx];
    }
    float myh = 0.f;                 // this thread's hidden value (tid < nr)
    __syncthreads();

    unsigned cache[8];
#pragma unroll
    for (int j = 0; j < 8; ++j) cache[j] = 0u;

    for (int s = 1; s <= T_STEPS; ++s) {
        float* orow = out + (size_t)(s - 1) * HID;
        if ((s & pmask) == 0u) {
            // xproj prefetch (independent of the dependency wait)
            if (tid < nr) xv[tid] = g_xproj[(size_t)(s - 1) * HID + r0 + tid];

            // tid0 polls per-module completion counters (mostly cached)
            if (tid == 0) {
#pragma unroll
                for (int j = 0; j < 8; ++j) {
                    int u = (s - 1) & ~((1 << j) - 1);
                    unsigned need = (unsigned)c_n[j] * (unsigned)(u >> j);
                    while (cache[j] < need) cache[j] = ld_acq(&g_cnt[j]);
                }
            }
            __syncthreads();

            if (regpath) {
                // warp wid owns h-chunk wid (cols 256*wid .. +255); thread: 8 cols
                int u = (s - 1) & ~((1 << wid) - 1);
                float4 ha, hb;
                if (u > 0) {
                    const float4* hp = (const float4*)(out + (size_t)(u - 1) * HID + 8 * tid);
                    ha = hp[0]; hb = hp[1];
                } else {
                    ha = make_float4(0.f, 0.f, 0.f, 0.f); hb = ha;
                }
                float acc[RCAP];
#pragma unroll
                for (int r = 0; r < RCAP; ++r)
                    if (r < nr) {
                        float4 wa = Wa[r], wb = Wb[r];
                        acc[r] = wa.x * ha.x + wa.y * ha.y + wa.z * ha.z + wa.w * ha.w
                               + wb.x * hb.x + wb.y * hb.y + wb.z * hb.z + wb.w * hb.w;
                    }
#pragma unroll
                for (int r = 0; r < RCAP; ++r)
                    if (r < nr) {
                        float v = acc[r];
                        v += __shfl_xor_sync(0xffffffffu, v, 16);
                        v += __shfl_xor_sync(0xffffffffu, v, 8);
                        v += __shfl_xor_sync(0xffffffffu, v, 4);
                        v += __shfl_xor_sync(0xffffffffu, v, 2);
                        v += __shfl_xor_sync(0xffffffffu, v, 1);
                        if (lane == 0) redp[r * 8 + wid] = v;
                    }
                __syncthreads();
                if (wid * 32 < nr * 8) {
                    float v = (tid < nr * 8) ? redp[tid] : 0.f;
                    v += __shfl_down_sync(0xffffffffu, v, 4, 8);
                    v += __shfl_down_sync(0xffffffffu, v, 2, 8);
                    v += __shfl_down_sync(0xffffffffu, v, 1, 8);
                    if ((tid & 7) == 0 && tid < nr * 8)
                        hloc[tid >> 3] = tanhf(v + xv[tid >> 3]);
                }
                __syncthreads();
            } else {
                // gather full h(t-1) into SMEM (per-chunk source rows)
#pragma unroll
                for (int half = 0; half < 2; ++half) {
                    int g = tid + half * 256;             // float4 index 0..511
                    int j = g >> 6;                        // chunk
                    int u = (s - 1) & ~((1 << j) - 1);
                    float4 v = make_float4(0.f, 0.f, 0.f, 0.f);
                    if (u > 0) v = ((const float4*)(out + (size_t)(u - 1) * HID))[g];
                    ((float4*)hsm)[g] = v;
                }
                __syncthreads();
                for (int r = wid; r < nr; r += 8) {
                    const float4* wr = (const float4*)(Wsm + (size_t)r * HID);
                    const float4* hv = (const float4*)hsm;
                    float a0 = 0.f, a1 = 0.f, a2 = 0.f, a3 = 0.f;
#pragma unroll
                    for (int it = 0; it < 16; ++it) {
                        float4 w4 = wr[lane + 32 * it];
                        float4 h4 = hv[lane + 32 * it];
                        a0 += w4.x * h4.x; a1 += w4.y * h4.y;
                        a2 += w4.z * h4.z; a3 += w4.w * h4.w;
                    }
                    float acc = (a0 + a1) + (a2 + a3);
                    acc += __shfl_xor_sync(0xffffffffu, acc, 16);
                    acc += __shfl_xor_sync(0xffffffffu, acc, 8);
                    acc += __shfl_xor_sync(0xffffffffu, acc, 4);
                    acc += __shfl_xor_sync(0xffffffffu, acc, 2);
                    acc += __shfl_xor_sync(0xffffffffu, acc, 1);
                    if (lane == 0) hloc[r] = tanhf(acc + xv[r]);
                }
                __syncthreads();
            }
            if (tid < nr) {
                myh = hloc[tid];
                orow[r0 + tid] = myh;
            }
            __syncthreads();
            if (tid == 0) red_rel_add(&g_cnt[m], 1u);
        } else {
            // inactive: copy-forward only; races ahead, off the critical path
            if (tid < nr) orow[r0 + tid] = myh;
        }
    }
}

// ---------------- launch ----------------
extern "C" void kernel_launch(void* const* d_in, const int* in_sizes, int n_in,
                              void* d_out, int out_size) {
    const float* x    = (const float*)d_in[0];
    const float* Wih  = (const float*)d_in[1];
    const float* Whh  = (const float*)d_in[2];
    const float* b_ih = (const float*)d_in[3];
    const float* b_hh = (const float*)d_in[4];
    float* out = (float*)d_out;

    static bool attr_set = false;
    const int smem_bytes = (MAXROWS * HID + HID + 32 + 32 + RCAP * 8) * (int)sizeof(float);
    if (!attr_set) {
        cudaFuncSetAttribute(cwrnn_recur,
                             cudaFuncAttributeMaxDynamicSharedMemorySize, smem_bytes);
        attr_set = true;
    }

    reset_cnt<<<1, 32>>>();
    gemm_xproj<<<dim3(HID / BN, T_STEPS / BM), 256>>>(x, Wih, b_ih, b_hh);
    cwrnn_recur<<<NCTA, NTHR, smem_bytes>>>(Whh, out);
}